// round 15
// baseline (speedup 1.0000x reference)
#include <cuda_runtime.h>
#include <cuda_bf16.h>
#include <math.h>
#include <stdint.h>

#define CTX      1024
#define BROWS    16
#define TOTAL_S  320
#define NF       256
#define D_MODEL  256
#define NHEADS   16
#define DK       16
#define DFF      1024
#define NLAYERS  4
#define TGT      96
#define SEQ      (BROWS * TOTAL_S)   // 5120
#define ATTN_SCALE 0.25f
#define LN_EPS   1e-5f
#define NBH      (BROWS * NHEADS)    // 256

// ---------------------------------------------------------------------------
// warp MMA + cp.async + f32x2 helpers
// ---------------------------------------------------------------------------
__device__ __forceinline__ uint32_t smem_u32(const void* p) {
    uint32_t a;
    asm("{ .reg .u64 t; cvta.to.shared.u64 t, %1; cvt.u32.u64 %0, t; }"
        : "=r"(a) : "l"(p));
    return a;
}
__device__ __forceinline__ void ldsm_x4(uint32_t& r0, uint32_t& r1,
                                        uint32_t& r2, uint32_t& r3, uint32_t addr) {
    asm volatile("ldmatrix.sync.aligned.m8n8.x4.shared.b16 {%0,%1,%2,%3}, [%4];"
                 : "=r"(r0), "=r"(r1), "=r"(r2), "=r"(r3) : "r"(addr));
}
__device__ __forceinline__ void mma_bf16(float* c, const uint32_t* a, const uint32_t* b) {
    asm volatile(
        "mma.sync.aligned.m16n8k16.row.col.f32.bf16.bf16.f32 "
        "{%0,%1,%2,%3}, {%4,%5,%6,%7}, {%8,%9}, {%0,%1,%2,%3};"
        : "+f"(c[0]), "+f"(c[1]), "+f"(c[2]), "+f"(c[3])
        : "r"(a[0]), "r"(a[1]), "r"(a[2]), "r"(a[3]), "r"(b[0]), "r"(b[1]));
}
#define CP_ASYNC16(dst, src) \
    asm volatile("cp.async.cg.shared.global [%0], [%1], 16;" :: "r"(dst), "l"(src))
#define CP_COMMIT() asm volatile("cp.async.commit_group;" ::: "memory")
#define CP_WAIT0()  asm volatile("cp.async.wait_group 0;" ::: "memory")

// packed f32x2 (Blackwell): 2 fp32 FMA per instruction
#define FFMA2(acc, a, b) \
    asm("fma.rn.f32x2 %0, %1, %2, %0;" : "+l"(acc) : "l"(a), "l"(b))
#define MUL2(out, a, b) \
    asm("mul.rn.f32x2 %0, %1, %2;" : "=l"(out) : "l"(a), "l"(b))
__device__ __forceinline__ unsigned long long pack2(float lo, float hi) {
    unsigned long long r;
    asm("mov.b64 %0, {%1, %2};" : "=l"(r) : "f"(lo), "f"(hi));
    return r;
}
__device__ __forceinline__ void unpack2(unsigned long long v, float& lo, float& hi) {
    asm("mov.b64 {%0, %1}, %2;" : "=f"(lo), "=f"(hi) : "l"(v));
}

// ---------------------------------------------------------------------------
// scratch
// ---------------------------------------------------------------------------
__device__ __align__(256) float g_u[SEQ * D_MODEL];
__device__ __align__(256) float g_qkv[SEQ * 768];
__device__ __align__(256) float g_tmp[SEQ * D_MODEL];
__device__ __align__(256) float g_scores[NBH * TOTAL_S * TOTAL_S]; // [bh][kk][q]
__device__ float g_mean[BROWS];
__device__ float g_std[BROWS];
__device__ __align__(256) float g_part[D_MODEL * BROWS * TGT];
__device__ __align__(256) float g_bqkv[NLAYERS * 768];

// split-softmax partials: [half][bh][q]
__device__ __align__(256) float g_apm[2 * NBH * TOTAL_S];
__device__ __align__(256) float g_apd[2 * NBH * TOTAL_S];
__device__ __align__(256) float g_apo[2 * NBH * TOTAL_S * DK];

__device__ __align__(256) __nv_bfloat16 g_u_hi[SEQ * D_MODEL];
__device__ __align__(256) __nv_bfloat16 g_u_lo[SEQ * D_MODEL];
__device__ __align__(256) __nv_bfloat16 g_o_hi[SEQ * D_MODEL];
__device__ __align__(256) __nv_bfloat16 g_o_lo[SEQ * D_MODEL];
__device__ __align__(256) __nv_bfloat16 g_h1_hi[SEQ * DFF];
__device__ __align__(256) __nv_bfloat16 g_h1_lo[SEQ * DFF];
#define WOFF_Q   0
#define WOFF_K   65536
#define WOFF_V   131072
#define WOFF_O   196608
#define WOFF_F1  262144
#define WOFF_F2  524288
#define WSTRIDE  786432
__device__ __align__(256) __nv_bfloat16 g_wt_hi[NLAYERS * WSTRIDE];
__device__ __align__(256) __nv_bfloat16 g_wt_lo[NLAYERS * WSTRIDE];

// ---------------------------------------------------------------------------
// merged preprocessing: weight transpose/split, bias pack, RevIN stats
// ---------------------------------------------------------------------------
__global__ __launch_bounds__(256) void wsplit_all_kernel(
    const float* __restrict__ WQ, const float* __restrict__ WK,
    const float* __restrict__ WV, const float* __restrict__ WO,
    const float* __restrict__ F1, const float* __restrict__ F2,
    const float* __restrict__ bQ, const float* __restrict__ bK,
    const float* __restrict__ bV, const float* __restrict__ z)
{
    int kind = blockIdx.y, l = blockIdx.z, tile = blockIdx.x;
    __shared__ float t[32][33];

    if (kind == 6) {
        if (tile >= 3) return;
        int i = tile * 256 + threadIdx.x;
        if (i >= 768) return;
        float v = (i < 256) ? bQ[l * 256 + i]
                : (i < 512) ? bK[l * 256 + i - 256]
                            : bV[l * 256 + i - 512];
        g_bqkv[l * 768 + i] = v;
        return;
    }
    if (kind == 7) {
        if (l != 0 || tile >= BROWS) return;
        int r = tile, tid = threadIdx.x;
        float s = 0.f, s2 = 0.f;
        for (int i = tid; i < CTX; i += 256) {
            float v = z[r * CTX + i];
            s += v; s2 += v * v;
        }
        float* rs = &t[0][0];
        float* rq = rs + 256;
        rs[tid] = s; rq[tid] = s2;
        __syncthreads();
        for (int o = 128; o; o >>= 1) {
            if (tid < o) { rs[tid] += rs[tid + o]; rq[tid] += rq[tid + o]; }
            __syncthreads();
        }
        if (tid == 0) {
            float m = rs[0] / CTX;
            float var = rq[0] / CTX - m * m;
            g_mean[r] = m;
            g_std[r]  = sqrtf(var + LN_EPS);
        }
        return;
    }

    const float* W; int R, C; size_t inl, ooff;
    switch (kind) {
        case 0: W = WQ; R = 256;  C = 256;  inl = 65536;  ooff = WOFF_Q;  break;
        case 1: W = WK; R = 256;  C = 256;  inl = 65536;  ooff = WOFF_K;  break;
        case 2: W = WV; R = 256;  C = 256;  inl = 65536;  ooff = WOFF_V;  break;
        case 3: W = WO; R = 256;  C = 256;  inl = 65536;  ooff = WOFF_O;  break;
        case 4: W = F1; R = 256;  C = 1024; inl = 262144; ooff = WOFF_F1; break;
        default: W = F2; R = 1024; C = 256; inl = 262144; ooff = WOFF_F2; break;
    }
    int ct = C >> 5, rt = R >> 5;
    if (tile >= ct * rt) return;
    int c0 = (tile % ct) << 5, r0 = (tile / ct) << 5;
    const float* Wl = W + (size_t)l * inl;

    int tx = threadIdx.x & 31, ty = threadIdx.x >> 5;
#pragma unroll
    for (int i = 0; i < 32; i += 8)
        t[ty + i][tx] = Wl[(size_t)(r0 + ty + i) * C + c0 + tx];
    __syncthreads();
#pragma unroll
    for (int i = 0; i < 32; i += 8) {
        float x = t[tx][ty + i];
        size_t oi = (size_t)l * WSTRIDE + ooff + (size_t)(c0 + ty + i) * R + (r0 + tx);
        __nv_bfloat16 h = __float2bfloat16(x);
        g_wt_hi[oi] = h;
        g_wt_lo[oi] = __float2bfloat16(x - __bfloat162float(h));
    }
}

// ---------------------------------------------------------------------------
__global__ __launch_bounds__(256) void embed_kernel(
    const float* __restrict__ z,
    const float* __restrict__ revin_w, const float* __restrict__ revin_b,
    const float* __restrict__ Wf, const float* __restrict__ bf,
    const float* __restrict__ Wc, const float* __restrict__ bcoarse,
    const float* __restrict__ Wpos)
{
    int bch = blockIdx.y;
    int s   = blockIdx.x;
    int d   = threadIdx.x;
    int c   = bch & 7;

    __shared__ float patch[32];
    int plen, stride, p;
    const float* W; const float* bias;
    if (s < NF) { plen = 8;  stride = 4;  p = s;      W = Wf; bias = bf; }
    else        { plen = 32; stride = 16; p = s - NF; W = Wc; bias = bcoarse; }

    if (d < plen) {
        int t = p * stride + d;
        if (t > CTX - 1) t = CTX - 1;
        float zv = z[bch * CTX + t];
        patch[d] = (zv - g_mean[bch]) / g_std[bch] * revin_w[c] + revin_b[c];
    }
    __syncthreads();

    float acc = bias[d] + Wpos[s * D_MODEL + d];
    for (int i = 0; i < plen; i++) acc += patch[i] * W[i * D_MODEL + d];
    size_t idx = (size_t)(bch * TOTAL_S + s) * D_MODEL + d;
    g_u[idx] = acc;
    __nv_bfloat16 h = __float2bfloat16(acc);
    g_u_hi[idx] = h;
    g_u_lo[idx] = __float2bfloat16(acc - __bfloat162float(h));
}

// ---------------------------------------------------------------------------
// HMMA bf16x3 GEMM, cp.async 2-stage pipeline, K-chunk 64, MT=64.
// ---------------------------------------------------------------------------
#define ASTRIDE 72

template<int EPI, int MT>
__global__ __launch_bounds__(256) void gemm_tc(
    const __nv_bfloat16* __restrict__ Ah, const __nv_bfloat16* __restrict__ Al,
    const __nv_bfloat16* __restrict__ Bh, const __nv_bfloat16* __restrict__ Bl,
    const float* __restrict__ bias,
    float* __restrict__ Cf,
    __nv_bfloat16* __restrict__ Chi, __nv_bfloat16* __restrict__ Clo,
    int N, int K)
{
    constexpr int WNs = (MT == 128) ? 2 : 4;
    constexpr int NT  = 16 / WNs;
    constexpr int BUF_A = MT * ASTRIDE * 2;
    constexpr int BUF_B = 128 * ASTRIDE * 2;
    constexpr int STAGE = 2 * BUF_A + 2 * BUF_B;

    extern __shared__ char smem[];
    const uint32_t sbase = smem_u32(smem);

    const int tid = threadIdx.x;
    const int bm = blockIdx.y * MT, bn = blockIdx.x * 128;
    const int warp = tid >> 5, lane = tid & 31;
    const int wm = warp / WNs, wn = warp % WNs;

    const int sr = tid >> 3, sc = (tid & 7) * 8;

    float acc[2][NT][4];
#pragma unroll
    for (int mt = 0; mt < 2; mt++)
#pragma unroll
        for (int nt = 0; nt < NT; nt++)
#pragma unroll
            for (int i = 0; i < 4; i++) acc[mt][nt][i] = 0.f;

    const int gg = lane >> 3, l7 = lane & 7;
    const int a_row = (gg & 1) * 8 + l7;
    const int a_kb  = (gg >> 1) * 16;
    const int b_row = (gg >> 1) * 8 + l7;
    const int b_kb  = (gg & 1) * 16;

    const int nchunk = K >> 6;

#define STAGE_LOAD(kc, s) do { \
        const int _k0 = (kc) << 6; \
        uint32_t _base = sbase + (s) * STAGE; \
        _Pragma("unroll") \
        for (int i = 0; i < MT / 32; i++) { \
            int r = sr + i * 32; \
            uint32_t so = _base + r * 144 + sc * 2; \
            CP_ASYNC16(so, Ah + (size_t)(bm + r) * K + _k0 + sc); \
            CP_ASYNC16(so + BUF_A, Al + (size_t)(bm + r) * K + _k0 + sc); \
        } \
        _Pragma("unroll") \
        for (int i = 0; i < 4; i++) { \
            int r = sr + i * 32; \
            uint32_t so = _base + 2 * BUF_A + r * 144 + sc * 2; \
            CP_ASYNC16(so, Bh + (size_t)(bn + r) * K + _k0 + sc); \
            CP_ASYNC16(so + BUF_B, Bl + (size_t)(bn + r) * K + _k0 + sc); \
        } \
        CP_COMMIT(); \
    } while (0)

    STAGE_LOAD(0, 0);

    for (int kc = 0; kc < nchunk; kc++) {
        CP_WAIT0();
        __syncthreads();
        if (kc + 1 < nchunk) STAGE_LOAD(kc + 1, (kc + 1) & 1);

        const uint32_t base = sbase + (kc & 1) * STAGE;
        const uint32_t uAh = base, uAl = base + BUF_A;
        const uint32_t uBh = base + 2 * BUF_A, uBl = uBh + BUF_B;

#pragma unroll
        for (int ks = 0; ks < 4; ks++) {
            uint32_t ah[2][4], al[2][4], bh[NT][2], bl[NT][2];
#pragma unroll
            for (int mt = 0; mt < 2; mt++) {
                int row = wm * 32 + mt * 16 + a_row;
                uint32_t off = (uint32_t)(row * 144 + ks * 32 + a_kb);
                ldsm_x4(ah[mt][0], ah[mt][1], ah[mt][2], ah[mt][3], uAh + off);
                ldsm_x4(al[mt][0], al[mt][1], al[mt][2], al[mt][3], uAl + off);
            }
#pragma unroll
            for (int j = 0; j < NT / 2; j++) {
                int row = wn * (128 / WNs) + j * 16 + b_row;
                uint32_t off = (uint32_t)(row * 144 + ks * 32 + b_kb);
                uint32_t r0, r1, r2, r3;
                ldsm_x4(r0, r1, r2, r3, uBh + off);
                bh[2 * j][0] = r0; bh[2 * j][1] = r1;
                bh[2 * j + 1][0] = r2; bh[2 * j + 1][1] = r3;
                ldsm_x4(r0, r1, r2, r3, uBl + off);
                bl[2 * j][0] = r0; bl[2 * j][1] = r1;
                bl[2 * j + 1][0] = r2; bl[2 * j + 1][1] = r3;
            }
#pragma unroll
            for (int mt = 0; mt < 2; mt++)
#pragma unroll
                for (int nt = 0; nt < NT; nt++) {
                    mma_bf16(acc[mt][nt], ah[mt], bh[nt]);
                    mma_bf16(acc[mt][nt], ah[mt], bl[nt]);
                    mma_bf16(acc[mt][nt], al[mt], bh[nt]);
                }
        }
        __syncthreads();
    }
#undef STAGE_LOAD

#pragma unroll
    for (int mt = 0; mt < 2; mt++) {
        int row0 = bm + wm * 32 + mt * 16 + (lane >> 2);
#pragma unroll
        for (int nt = 0; nt < NT; nt++) {
            int col = bn + wn * (128 / WNs) + nt * 8 + (lane & 3) * 2;
            float b0 = bias[col], b1 = bias[col + 1];
            float v0 = acc[mt][nt][0] + b0, v1 = acc[mt][nt][1] + b1;
            float v2 = acc[mt][nt][2] + b0, v3 = acc[mt][nt][3] + b1;
            if (EPI == 0) {
                float2 p0 = {v0, v1}, p1 = {v2, v3};
                *(float2*)&Cf[(size_t)row0 * N + col] = p0;
                *(float2*)&Cf[(size_t)(row0 + 8) * N + col] = p1;
            } else {
                v0 = 0.5f * v0 * (1.0f + erff(v0 * 0.7071067811865475f));
                v1 = 0.5f * v1 * (1.0f + erff(v1 * 0.7071067811865475f));
                v2 = 0.5f * v2 * (1.0f + erff(v2 * 0.7071067811865475f));
                v3 = 0.5f * v3 * (1.0f + erff(v3 * 0.7071067811865475f));
                __nv_bfloat162 hh, ll;
                hh.x = __float2bfloat16(v0); hh.y = __float2bfloat16(v1);
                ll.x = __float2bfloat16(v0 - __bfloat162float(hh.x));
                ll.y = __float2bfloat16(v1 - __bfloat162float(hh.y));
                *(__nv_bfloat162*)&Chi[(size_t)row0 * N + col] = hh;
                *(__nv_bfloat162*)&Clo[(size_t)row0 * N + col] = ll;
                hh.x = __float2bfloat16(v2); hh.y = __float2bfloat16(v3);
                ll.x = __float2bfloat16(v2 - __bfloat162float(hh.x));
                ll.y = __float2bfloat16(v3 - __bfloat162float(hh.y));
                *(__nv_bfloat162*)&Chi[(size_t)(row0 + 8) * N + col] = hh;
                *(__nv_bfloat162*)&Clo[(size_t)(row0 + 8) * N + col] = ll;
            }
        }
    }
}

// ---------------------------------------------------------------------------
// fused attention v5: split-softmax over kk halves.
// grid (2 halves, 256 bh), block 320, one q-row per thread.
// Each CTA: 160 kk, online softmax, writes unnormalized partials (m, den, o).
// Scores [bh][kk][q] residual r/w: each half owns its own kk rows.
// ---------------------------------------------------------------------------
#define ATTN_SMEM ((2 * 160 * DK + TOTAL_S * DK) * 4)   // 40960 B

__global__ __launch_bounds__(320) void attn_split_kernel(int use_prev, int wr)
{
    extern __shared__ float asm_f[];
    float* Ks = asm_f;                 // [160][16]
    float* Vs = Ks + 160 * DK;
    float* Qs = Vs + 160 * DK;         // [320][16]

    int half = blockIdx.x, bh = blockIdx.y;
    int bc = bh >> 4, h = bh & 15;
    int k0 = half * 160;
    int tid = threadIdx.x;             // q-row

    for (int i = tid; i < 160 * 4; i += 320) {
        int s = i >> 2, c = i & 3;
        const float4* src = (const float4*)&g_qkv[(size_t)(bc * TOTAL_S + k0 + s) * 768 + (h << 4)];
        *(float4*)&Ks[s * DK + c * 4] = src[64 + c];
        *(float4*)&Vs[s * DK + c * 4] = src[128 + c];
    }
    for (int i = tid; i < TOTAL_S * 4; i += 320) {
        int s = i >> 2, c = i & 3;
        const float4* src = (const float4*)&g_qkv[(size_t)(bc * TOTAL_S + s) * 768 + (h << 4)];
        *(float4*)&Qs[s * DK + c * 4] = src[c];
    }
    __syncthreads();

    unsigned long long q2[8];
    {
        const ulonglong2* qp = (const ulonglong2*)&Qs[tid * DK];
#pragma unroll
        for (int c = 0; c < 4; c++) {
            ulonglong2 v = qp[c];
            q2[2 * c] = v.x; q2[2 * c + 1] = v.y;
        }
    }

    float m = -1e30f, den = 0.f;
    unsigned long long o2[8];
#pragma unroll
    for (int c = 0; c < 8; c++) o2[c] = 0ULL;

    float* srow = &g_scores[(size_t)bh * TOTAL_S * TOTAL_S];  // [kk][q]

#pragma unroll 1
    for (int blk = 0; blk < 20; blk++) {
        float sc[8];
#pragma unroll
        for (int t = 0; t < 8; t++) {
            int kl = blk * 8 + t;          // local kk
            int kk = k0 + kl;
            const ulonglong2* kp = (const ulonglong2*)&Ks[kl * DK];
            unsigned long long acc2 = 0ULL;
#pragma unroll
            for (int c = 0; c < 4; c++) {
                ulonglong2 kv = kp[c];                  // broadcast LDS.128
                FFMA2(acc2, q2[2 * c], kv.x);
                FFMA2(acc2, q2[2 * c + 1], kv.y);
            }
            float lo, hi; unpack2(acc2, lo, hi);
            float s = (lo + hi) * ATTN_SCALE;
            if (use_prev) s += srow[(size_t)kk * TOTAL_S + tid];
            sc[t] = s;
            if (wr) srow[(size_t)kk * TOTAL_S + tid] = s;
        }
        float bm = sc[0];
#pragma unroll
        for (int t = 1; t < 8; t++) bm = fmaxf(bm, sc[t]);
        float mn = fmaxf(m, bm);
        float corr = __expf(m - mn);
        den *= corr;
        unsigned long long c2 = pack2(corr, corr);
#pragma unroll
        for (int c = 0; c < 8; c++) MUL2(o2[c], o2[c], c2);
#pragma unroll
        for (int t = 0; t < 8; t++) {
            int kl = blk * 8 + t;
            float p = __expf(sc[t] - mn);
            den += p;
            unsigned long long p2 = pack2(p, p);
            const ulonglong2* vp = (const ulonglong2*)&Vs[kl * DK];
#pragma unroll
            for (int c = 0; c < 4; c++) {
                ulonglong2 vv = vp[c];                  // broadcast LDS.128
                FFMA2(o2[2 * c], p2, vv.x);
                FFMA2(o2[2 * c + 1], p2, vv.y);
            }
        }
        m = mn;
    }

    size_t pidx = ((size_t)half * NBH + bh) * TOTAL_S + tid;
    g_apm[pidx] = m;
    g_apd[pidx] = den;
    float2* po = (float2*)&g_apo[pidx * DK];
#pragma unroll
    for (int c = 0; c < 8; c++) {
        float v0, v1; unpack2(o2[c], v0, v1);
        po[c] = make_float2(v0, v1);
    }
}

// merge two softmax halves -> o (bf16 hi/lo)
__global__ __launch_bounds__(256) void attn_merge_kernel()
{
    int idx = blockIdx.x * 256 + threadIdx.x;
    if (idx >= NBH * TOTAL_S) return;
    int bh = idx / TOTAL_S, q = idx % TOTAL_S;
    int bc = bh >> 4, h = bh & 15;
    size_t i0 = (size_t)bh * TOTAL_S + q;
    size_t i1 = (size_t)NBH * TOTAL_S + i0;
    float m0 = g_apm[i0], m1 = g_apm[i1];
    float d0 = g_apd[i0], d1 = g_apd[i1];
    float m = fmaxf(m0, m1);
    float c0 = __expf(m0 - m), c1 = __expf(m1 - m);
    float inv = 1.f / (d0 * c0 + d1 * c1);
    float w0 = c0 * inv, w1 = c1 * inv;
    const float2* o0 = (const float2*)&g_apo[i0 * DK];
    const float2* o1 = (const float2*)&g_apo[i1 * DK];
    size_t ob = (size_t)(bc * TOTAL_S + q) * D_MODEL + (h << 4);
#pragma unroll
    for (int c = 0; c < 8; c++) {
        float2 a = o0[c], b = o1[c];
        float v0 = a.x * w0 + b.x * w1;
        float v1 = a.y * w0 + b.y * w1;
        __nv_bfloat162 hh, ll;
        hh.x = __float2bfloat16(v0); hh.y = __float2bfloat16(v1);
        ll.x = __float2bfloat16(v0 - __bfloat162float(hh.x));
        ll.y = __float2bfloat16(v1 - __bfloat162float(hh.y));
        *(__nv_bfloat162*)&g_o_hi[ob + c * 2] = hh;
        *(__nv_bfloat162*)&g_o_lo[ob + c * 2] = ll;
    }
}

// ---------------------------------------------------------------------------
__global__ __launch_bounds__(256) void resid_ln_kernel(
    const float* __restrict__ delta,
    const float* __restrict__ gs, const float* __restrict__ gb)
{
    int row = blockIdx.x;
    int d = threadIdx.x;
    int warp = d >> 5, lane = d & 31;
    size_t idx = (size_t)row * D_MODEL + d;
    float t = g_u[idx] + delta[idx];

    __shared__ float sred[8];
    float ws = t;
#pragma unroll
    for (int o = 16; o; o >>= 1) ws += __shfl_xor_sync(0xffffffffu, ws, o);
    if (lane == 0) sred[warp] = ws;
    __syncthreads();
    float tot = 0.f;
#pragma unroll
    for (int i = 0; i < 8; i++) tot += sred[i];
    float mean = tot * (1.0f / D_MODEL);
    __syncthreads();

    float df = t - mean;
    ws = df * df;
#pragma unroll
    for (int o = 16; o; o >>= 1) ws += __shfl_xor_sync(0xffffffffu, ws, o);
    if (lane == 0) sred[warp] = ws;
    __syncthreads();
    tot = 0.f;
#pragma unroll
    for (int i = 0; i < 8; i++) tot += sred[i];
    float var = tot * (1.0f / D_MODEL);

    float y = df * rsqrtf(var + LN_EPS) * gs[d] + gb[d];
    g_u[idx] = y;
    __nv_bfloat16 h = __float2bfloat16(y);
    g_u_hi[idx] = h;
    g_u_lo[idx] = __float2bfloat16(y - __bfloat162float(h));
}

// ---------------------------------------------------------------------------
__global__ __launch_bounds__(96) void head_partial_kernel(const float* __restrict__ Wh)
{
    int d = blockIdx.x;
    int t = threadIdx.x;
    __shared__ float usm[BROWS][TOTAL_S];
    for (int i = t; i < BROWS * TOTAL_S; i += 96) {
        int bcc = i / TOTAL_S, s = i % TOTAL_S;
        usm[bcc][s] = g_u[(size_t)(bcc * TOTAL_S + s) * D_MODEL + d];
    }
    __syncthreads();
    float acc[BROWS];
#pragma unroll
    for (int b = 0; b < BROWS; b++) acc[b] = 0.f;
    for (int s = 0; s < TOTAL_S; s++) {
        float w = Wh[((size_t)d * TOTAL_S + s) * TGT + t];
#pragma unroll
        for (int b = 0; b < BROWS; b++) acc[b] += usm[b][s] * w;
    }
#pragma unroll
    for (int b = 0; b < BROWS; b++)
        g_part[((size_t)d * BROWS + b) * TGT + t] = acc[b];
}

__global__ __launch_bounds__(256) void head_reduce_kernel(
    const float* __restrict__ bh,
    const float* __restrict__ revin_w, const float* __restrict__ revin_b,
    float* __restrict__ out)
{
    int idx = blockIdx.x * blockDim.x + threadIdx.x;
    if (idx >= BROWS * TGT) return;
    int bcc = idx / TGT, t = idx % TGT;
    float acc = 0.f;
    for (int d = 0; d < D_MODEL; d++)
        acc += g_part[((size_t)d * BROWS + bcc) * TGT + t];
    acc += bh[t];
    int c = bcc & 7;
    out[idx] = (acc - revin_b[c]) / (revin_w[c] + 1e-10f) * g_std[bcc] + g_mean[bcc];
}

// ---------------------------------------------------------------------------
extern "C" void kernel_launch(void* const* d_in, const int* in_sizes, int n_in,
                              void* d_out, int out_size)
{
    const float* z       = (const float*)d_in[0];
    const float* revin_w = (const float*)d_in[1];
    const float* revin_b = (const float*)d_in[2];
    const float* Wf      = (const float*)d_in[3];
    const float* bf      = (const float*)d_in[4];
    const float* Wc      = (const float*)d_in[5];
    const float* bcoarse = (const float*)d_in[6];
    const float* Wpos    = (const float*)d_in[7];
    const float* WQ      = (const float*)d_in[8];
    const float* bQ      = (const float*)d_in[9];
    const float* WK      = (const float*)d_in[10];
    const float* bK      = (const float*)d_in[11];
    const float* WV      = (const float*)d_in[12];
    const float* bV      = (const float*)d_in[13];
    const float* WO      = (const float*)d_in[14];
    const float* bO      = (const float*)d_in[15];
    const float* ln1_s   = (const float*)d_in[16];
    const float* ln1_b   = (const float*)d_in[17];
    const float* ln2_s   = (const float*)d_in[18];
    const float* ln2_b   = (const float*)d_in[19];
    const float* F1      = (const float*)d_in[20];
    const float* c1      = (const float*)d_in[21];
    const float* F2      = (const float*)d_in[22];
    const float* c2      = (const float*)d_in[23];
    const float* Wh      = (const float*)d_in[24];
    const float* bh      = (const float*)d_in[25];
    float* out = (float*)d_out;

    float *u, *qkv, *tmp, *bqkv;
    __nv_bfloat16 *uh, *ul, *oh, *ol, *h1h, *h1l, *wth, *wtl;
    cudaGetSymbolAddress((void**)&u,    g_u);
    cudaGetSymbolAddress((void**)&qkv,  g_qkv);
    cudaGetSymbolAddress((void**)&tmp,  g_tmp);
    cudaGetSymbolAddress((void**)&bqkv, g_bqkv);
    cudaGetSymbolAddress((void**)&uh,   g_u_hi);
    cudaGetSymbolAddress((void**)&ul,   g_u_lo);
    cudaGetSymbolAddress((void**)&oh,   g_o_hi);
    cudaGetSymbolAddress((void**)&ol,   g_o_lo);
    cudaGetSymbolAddress((void**)&h1h,  g_h1_hi);
    cudaGetSymbolAddress((void**)&h1l,  g_h1_lo);
    cudaGetSymbolAddress((void**)&wth,  g_wt_hi);
    cudaGetSymbolAddress((void**)&wtl,  g_wt_lo);

    const int SMEM64 = 2 * (2 * 64 * ASTRIDE * 2 + 2 * 128 * ASTRIDE * 2);  // 110592
    cudaFuncSetAttribute(gemm_tc<0,64>, cudaFuncAttributeMaxDynamicSharedMemorySize, SMEM64);
    cudaFuncSetAttribute(gemm_tc<1,64>, cudaFuncAttributeMaxDynamicSharedMemorySize, SMEM64);
    cudaFuncSetAttribute(attn_split_kernel, cudaFuncAttributeMaxDynamicSharedMemorySize, ATTN_SMEM);

    // launch order: 0 wsplit(+bias+stats), 1 embed, 2 QKV gemm, 3 attn_split
    wsplit_all_kernel<<<dim3(256, 8, NLAYERS), 256>>>(WQ, WK, WV, WO, F1, F2,
                                                      bQ, bK, bV, z);
    embed_kernel<<<dim3(TOTAL_S, BROWS), 256>>>(z, revin_w, revin_b,
                                                Wf, bf, Wc, bcoarse, Wpos);

    for (int l = 0; l < NLAYERS; l++) {
        const size_t L = (size_t)l * WSTRIDE;
        gemm_tc<0,64><<<dim3(6, 80), 256, SMEM64>>>(
            uh, ul, wth + L + WOFF_Q, wtl + L + WOFF_Q,
            bqkv + l * 768, qkv, nullptr, nullptr, 768, D_MODEL);
        attn_split_kernel<<<dim3(2, NBH), 320, ATTN_SMEM>>>(
            l > 0 ? 1 : 0, l < NLAYERS - 1 ? 1 : 0);
        attn_merge_kernel<<<(NBH * TOTAL_S + 255) / 256, 256>>>();
        gemm_tc<0,64><<<dim3(2, 80), 256, SMEM64>>>(
            oh, ol, wth + L + WOFF_O, wtl + L + WOFF_O,
            bO + l * D_MODEL, tmp, nullptr, nullptr, D_MODEL, D_MODEL);
        resid_ln_kernel<<<SEQ, 256>>>(tmp, ln1_s + l * D_MODEL, ln1_b + l * D_MODEL);
        gemm_tc<1,64><<<dim3(8, 80), 256, SMEM64>>>(
            uh, ul, wth + L + WOFF_F1, wtl + L + WOFF_F1,
            c1 + l * DFF, nullptr, h1h, h1l, DFF, D_MODEL);
        gemm_tc<0,64><<<dim3(2, 80), 256, SMEM64>>>(
            h1h, h1l, wth + L + WOFF_F2, wtl + L + WOFF_F2,
            c2 + l * D_MODEL, tmp, nullptr, nullptr, D_MODEL, DFF);
        resid_ln_kernel<<<SEQ, 256>>>(tmp, ln2_s + l * D_MODEL, ln2_b + l * D_MODEL);
    }

    head_partial_kernel<<<D_MODEL, 96>>>(Wh);
    head_reduce_kernel<<<6, 256>>>(bh, revin_w, revin_b, out);
}

// round 16
// speedup vs baseline: 1.2380x; 1.2380x over previous
#include <cuda_runtime.h>
#include <cuda_bf16.h>
#include <math.h>
#include <stdint.h>

#define CTX      1024
#define BROWS    16
#define TOTAL_S  320
#define NF       256
#define D_MODEL  256
#define NHEADS   16
#define DK       16
#define DFF      1024
#define NLAYERS  4
#define TGT      96
#define SEQ      (BROWS * TOTAL_S)   // 5120
#define ATTN_SCALE 0.25f
#define LN_EPS   1e-5f

// ---------------------------------------------------------------------------
// warp MMA + cp.async + f32x2 helpers
// ---------------------------------------------------------------------------
__device__ __forceinline__ uint32_t smem_u32(const void* p) {
    uint32_t a;
    asm("{ .reg .u64 t; cvta.to.shared.u64 t, %1; cvt.u32.u64 %0, t; }"
        : "=r"(a) : "l"(p));
    return a;
}
__device__ __forceinline__ void ldsm_x4(uint32_t& r0, uint32_t& r1,
                                        uint32_t& r2, uint32_t& r3, uint32_t addr) {
    asm volatile("ldmatrix.sync.aligned.m8n8.x4.shared.b16 {%0,%1,%2,%3}, [%4];"
                 : "=r"(r0), "=r"(r1), "=r"(r2), "=r"(r3) : "r"(addr));
}
__device__ __forceinline__ void mma_bf16(float* c, const uint32_t* a, const uint32_t* b) {
    asm volatile(
        "mma.sync.aligned.m16n8k16.row.col.f32.bf16.bf16.f32 "
        "{%0,%1,%2,%3}, {%4,%5,%6,%7}, {%8,%9}, {%0,%1,%2,%3};"
        : "+f"(c[0]), "+f"(c[1]), "+f"(c[2]), "+f"(c[3])
        : "r"(a[0]), "r"(a[1]), "r"(a[2]), "r"(a[3]), "r"(b[0]), "r"(b[1]));
}
#define CP_ASYNC16(dst, src) \
    asm volatile("cp.async.cg.shared.global [%0], [%1], 16;" :: "r"(dst), "l"(src))
#define CP_COMMIT() asm volatile("cp.async.commit_group;" ::: "memory")
#define CP_WAIT0()  asm volatile("cp.async.wait_group 0;" ::: "memory")

// packed f32x2 (Blackwell): 2 fp32 FMA per instruction
#define FFMA2(acc, a, b) \
    asm("fma.rn.f32x2 %0, %1, %2, %0;" : "+l"(acc) : "l"(a), "l"(b))
#define MUL2(out, a, b) \
    asm("mul.rn.f32x2 %0, %1, %2;" : "=l"(out) : "l"(a), "l"(b))
__device__ __forceinline__ unsigned long long pack2(float lo, float hi) {
    unsigned long long r;
    asm("mov.b64 %0, {%1, %2};" : "=l"(r) : "f"(lo), "f"(hi));
    return r;
}
__device__ __forceinline__ void unpack2(unsigned long long v, float& lo, float& hi) {
    asm("mov.b64 {%0, %1}, %2;" : "=f"(lo), "=f"(hi) : "l"(v));
}

// ---------------------------------------------------------------------------
// scratch
// ---------------------------------------------------------------------------
__device__ __align__(256) float g_u[SEQ * D_MODEL];
__device__ __align__(256) float g_qkv[SEQ * 768];
__device__ __align__(256) float g_tmp[SEQ * D_MODEL];
__device__ __align__(256) float g_scores[BROWS * NHEADS * TOTAL_S * TOTAL_S]; // [bh][kk][q]
__device__ float g_mean[BROWS];
__device__ float g_std[BROWS];
__device__ __align__(256) float g_part[D_MODEL * BROWS * TGT];
__device__ __align__(256) float g_bqkv[NLAYERS * 768];

__device__ __align__(256) __nv_bfloat16 g_u_hi[SEQ * D_MODEL];
__device__ __align__(256) __nv_bfloat16 g_u_lo[SEQ * D_MODEL];
__device__ __align__(256) __nv_bfloat16 g_o_hi[SEQ * D_MODEL];
__device__ __align__(256) __nv_bfloat16 g_o_lo[SEQ * D_MODEL];
__device__ __align__(256) __nv_bfloat16 g_h1_hi[SEQ * DFF];
__device__ __align__(256) __nv_bfloat16 g_h1_lo[SEQ * DFF];
#define WOFF_Q   0
#define WOFF_K   65536
#define WOFF_V   131072
#define WOFF_O   196608
#define WOFF_F1  262144
#define WOFF_F2  524288
#define WSTRIDE  786432
__device__ __align__(256) __nv_bfloat16 g_wt_hi[NLAYERS * WSTRIDE];
__device__ __align__(256) __nv_bfloat16 g_wt_lo[NLAYERS * WSTRIDE];

// ---------------------------------------------------------------------------
// merged preprocessing: weight transpose/split, bias pack, RevIN stats
// ---------------------------------------------------------------------------
__global__ __launch_bounds__(256) void wsplit_all_kernel(
    const float* __restrict__ WQ, const float* __restrict__ WK,
    const float* __restrict__ WV, const float* __restrict__ WO,
    const float* __restrict__ F1, const float* __restrict__ F2,
    const float* __restrict__ bQ, const float* __restrict__ bK,
    const float* __restrict__ bV, const float* __restrict__ z)
{
    int kind = blockIdx.y, l = blockIdx.z, tile = blockIdx.x;
    __shared__ float t[32][33];

    if (kind == 6) {
        if (tile >= 3) return;
        int i = tile * 256 + threadIdx.x;
        if (i >= 768) return;
        float v = (i < 256) ? bQ[l * 256 + i]
                : (i < 512) ? bK[l * 256 + i - 256]
                            : bV[l * 256 + i - 512];
        g_bqkv[l * 768 + i] = v;
        return;
    }
    if (kind == 7) {
        if (l != 0 || tile >= BROWS) return;
        int r = tile, tid = threadIdx.x;
        float s = 0.f, s2 = 0.f;
        for (int i = tid; i < CTX; i += 256) {
            float v = z[r * CTX + i];
            s += v; s2 += v * v;
        }
        float* rs = &t[0][0];
        float* rq = rs + 256;
        rs[tid] = s; rq[tid] = s2;
        __syncthreads();
        for (int o = 128; o; o >>= 1) {
            if (tid < o) { rs[tid] += rs[tid + o]; rq[tid] += rq[tid + o]; }
            __syncthreads();
        }
        if (tid == 0) {
            float m = rs[0] / CTX;
            float var = rq[0] / CTX - m * m;
            g_mean[r] = m;
            g_std[r]  = sqrtf(var + LN_EPS);
        }
        return;
    }

    const float* W; int R, C; size_t inl, ooff;
    switch (kind) {
        case 0: W = WQ; R = 256;  C = 256;  inl = 65536;  ooff = WOFF_Q;  break;
        case 1: W = WK; R = 256;  C = 256;  inl = 65536;  ooff = WOFF_K;  break;
        case 2: W = WV; R = 256;  C = 256;  inl = 65536;  ooff = WOFF_V;  break;
        case 3: W = WO; R = 256;  C = 256;  inl = 65536;  ooff = WOFF_O;  break;
        case 4: W = F1; R = 256;  C = 1024; inl = 262144; ooff = WOFF_F1; break;
        default: W = F2; R = 1024; C = 256; inl = 262144; ooff = WOFF_F2; break;
    }
    int ct = C >> 5, rt = R >> 5;
    if (tile >= ct * rt) return;
    int c0 = (tile % ct) << 5, r0 = (tile / ct) << 5;
    const float* Wl = W + (size_t)l * inl;

    int tx = threadIdx.x & 31, ty = threadIdx.x >> 5;
#pragma unroll
    for (int i = 0; i < 32; i += 8)
        t[ty + i][tx] = Wl[(size_t)(r0 + ty + i) * C + c0 + tx];
    __syncthreads();
#pragma unroll
    for (int i = 0; i < 32; i += 8) {
        float x = t[tx][ty + i];
        size_t oi = (size_t)l * WSTRIDE + ooff + (size_t)(c0 + ty + i) * R + (r0 + tx);
        __nv_bfloat16 h = __float2bfloat16(x);
        g_wt_hi[oi] = h;
        g_wt_lo[oi] = __float2bfloat16(x - __bfloat162float(h));
    }
}

// ---------------------------------------------------------------------------
__global__ __launch_bounds__(256) void embed_kernel(
    const float* __restrict__ z,
    const float* __restrict__ revin_w, const float* __restrict__ revin_b,
    const float* __restrict__ Wf, const float* __restrict__ bf,
    const float* __restrict__ Wc, const float* __restrict__ bcoarse,
    const float* __restrict__ Wpos)
{
    int bch = blockIdx.y;
    int s   = blockIdx.x;
    int d   = threadIdx.x;
    int c   = bch & 7;

    __shared__ float patch[32];
    int plen, stride, p;
    const float* W; const float* bias;
    if (s < NF) { plen = 8;  stride = 4;  p = s;      W = Wf; bias = bf; }
    else        { plen = 32; stride = 16; p = s - NF; W = Wc; bias = bcoarse; }

    if (d < plen) {
        int t = p * stride + d;
        if (t > CTX - 1) t = CTX - 1;
        float zv = z[bch * CTX + t];
        patch[d] = (zv - g_mean[bch]) / g_std[bch] * revin_w[c] + revin_b[c];
    }
    __syncthreads();

    float acc = bias[d] + Wpos[s * D_MODEL + d];
    for (int i = 0; i < plen; i++) acc += patch[i] * W[i * D_MODEL + d];
    size_t idx = (size_t)(bch * TOTAL_S + s) * D_MODEL + d;
    g_u[idx] = acc;
    __nv_bfloat16 h = __float2bfloat16(acc);
    g_u_hi[idx] = h;
    g_u_lo[idx] = __float2bfloat16(acc - __bfloat162float(h));
}

// ---------------------------------------------------------------------------
// HMMA bf16x3 GEMM, cp.async 2-stage pipeline, K-chunk 64, MT=64.
// ---------------------------------------------------------------------------
#define ASTRIDE 72

template<int EPI, int MT>
__global__ __launch_bounds__(256) void gemm_tc(
    const __nv_bfloat16* __restrict__ Ah, const __nv_bfloat16* __restrict__ Al,
    const __nv_bfloat16* __restrict__ Bh, const __nv_bfloat16* __restrict__ Bl,
    const float* __restrict__ bias,
    float* __restrict__ Cf,
    __nv_bfloat16* __restrict__ Chi, __nv_bfloat16* __restrict__ Clo,
    int N, int K)
{
    constexpr int WNs = (MT == 128) ? 2 : 4;
    constexpr int NT  = 16 / WNs;
    constexpr int BUF_A = MT * ASTRIDE * 2;
    constexpr int BUF_B = 128 * ASTRIDE * 2;
    constexpr int STAGE = 2 * BUF_A + 2 * BUF_B;

    extern __shared__ char smem[];
    const uint32_t sbase = smem_u32(smem);

    const int tid = threadIdx.x;
    const int bm = blockIdx.y * MT, bn = blockIdx.x * 128;
    const int warp = tid >> 5, lane = tid & 31;
    const int wm = warp / WNs, wn = warp % WNs;

    const int sr = tid >> 3, sc = (tid & 7) * 8;

    float acc[2][NT][4];
#pragma unroll
    for (int mt = 0; mt < 2; mt++)
#pragma unroll
        for (int nt = 0; nt < NT; nt++)
#pragma unroll
            for (int i = 0; i < 4; i++) acc[mt][nt][i] = 0.f;

    const int gg = lane >> 3, l7 = lane & 7;
    const int a_row = (gg & 1) * 8 + l7;
    const int a_kb  = (gg >> 1) * 16;
    const int b_row = (gg >> 1) * 8 + l7;
    const int b_kb  = (gg & 1) * 16;

    const int nchunk = K >> 6;

#define STAGE_LOAD(kc, s) do { \
        const int _k0 = (kc) << 6; \
        uint32_t _base = sbase + (s) * STAGE; \
        _Pragma("unroll") \
        for (int i = 0; i < MT / 32; i++) { \
            int r = sr + i * 32; \
            uint32_t so = _base + r * 144 + sc * 2; \
            CP_ASYNC16(so, Ah + (size_t)(bm + r) * K + _k0 + sc); \
            CP_ASYNC16(so + BUF_A, Al + (size_t)(bm + r) * K + _k0 + sc); \
        } \
        _Pragma("unroll") \
        for (int i = 0; i < 4; i++) { \
            int r = sr + i * 32; \
            uint32_t so = _base + 2 * BUF_A + r * 144 + sc * 2; \
            CP_ASYNC16(so, Bh + (size_t)(bn + r) * K + _k0 + sc); \
            CP_ASYNC16(so + BUF_B, Bl + (size_t)(bn + r) * K + _k0 + sc); \
        } \
        CP_COMMIT(); \
    } while (0)

    STAGE_LOAD(0, 0);

    for (int kc = 0; kc < nchunk; kc++) {
        CP_WAIT0();
        __syncthreads();
        if (kc + 1 < nchunk) STAGE_LOAD(kc + 1, (kc + 1) & 1);

        const uint32_t base = sbase + (kc & 1) * STAGE;
        const uint32_t uAh = base, uAl = base + BUF_A;
        const uint32_t uBh = base + 2 * BUF_A, uBl = uBh + BUF_B;

#pragma unroll
        for (int ks = 0; ks < 4; ks++) {
            uint32_t ah[2][4], al[2][4], bh[NT][2], bl[NT][2];
#pragma unroll
            for (int mt = 0; mt < 2; mt++) {
                int row = wm * 32 + mt * 16 + a_row;
                uint32_t off = (uint32_t)(row * 144 + ks * 32 + a_kb);
                ldsm_x4(ah[mt][0], ah[mt][1], ah[mt][2], ah[mt][3], uAh + off);
                ldsm_x4(al[mt][0], al[mt][1], al[mt][2], al[mt][3], uAl + off);
            }
#pragma unroll
            for (int j = 0; j < NT / 2; j++) {
                int row = wn * (128 / WNs) + j * 16 + b_row;
                uint32_t off = (uint32_t)(row * 144 + ks * 32 + b_kb);
                uint32_t r0, r1, r2, r3;
                ldsm_x4(r0, r1, r2, r3, uBh + off);
                bh[2 * j][0] = r0; bh[2 * j][1] = r1;
                bh[2 * j + 1][0] = r2; bh[2 * j + 1][1] = r3;
                ldsm_x4(r0, r1, r2, r3, uBl + off);
                bl[2 * j][0] = r0; bl[2 * j][1] = r1;
                bl[2 * j + 1][0] = r2; bl[2 * j + 1][1] = r3;
            }
#pragma unroll
            for (int mt = 0; mt < 2; mt++)
#pragma unroll
                for (int nt = 0; nt < NT; nt++) {
                    mma_bf16(acc[mt][nt], ah[mt], bh[nt]);
                    mma_bf16(acc[mt][nt], ah[mt], bl[nt]);
                    mma_bf16(acc[mt][nt], al[mt], bh[nt]);
                }
        }
        __syncthreads();
    }
#undef STAGE_LOAD

#pragma unroll
    for (int mt = 0; mt < 2; mt++) {
        int row0 = bm + wm * 32 + mt * 16 + (lane >> 2);
#pragma unroll
        for (int nt = 0; nt < NT; nt++) {
            int col = bn + wn * (128 / WNs) + nt * 8 + (lane & 3) * 2;
            float b0 = bias[col], b1 = bias[col + 1];
            float v0 = acc[mt][nt][0] + b0, v1 = acc[mt][nt][1] + b1;
            float v2 = acc[mt][nt][2] + b0, v3 = acc[mt][nt][3] + b1;
            if (EPI == 0) {
                float2 p0 = {v0, v1}, p1 = {v2, v3};
                *(float2*)&Cf[(size_t)row0 * N + col] = p0;
                *(float2*)&Cf[(size_t)(row0 + 8) * N + col] = p1;
            } else {
                v0 = 0.5f * v0 * (1.0f + erff(v0 * 0.7071067811865475f));
                v1 = 0.5f * v1 * (1.0f + erff(v1 * 0.7071067811865475f));
                v2 = 0.5f * v2 * (1.0f + erff(v2 * 0.7071067811865475f));
                v3 = 0.5f * v3 * (1.0f + erff(v3 * 0.7071067811865475f));
                __nv_bfloat162 hh, ll;
                hh.x = __float2bfloat16(v0); hh.y = __float2bfloat16(v1);
                ll.x = __float2bfloat16(v0 - __bfloat162float(hh.x));
                ll.y = __float2bfloat16(v1 - __bfloat162float(hh.y));
                *(__nv_bfloat162*)&Chi[(size_t)row0 * N + col] = hh;
                *(__nv_bfloat162*)&Clo[(size_t)row0 * N + col] = ll;
                hh.x = __float2bfloat16(v2); hh.y = __float2bfloat16(v3);
                ll.x = __float2bfloat16(v2 - __bfloat162float(hh.x));
                ll.y = __float2bfloat16(v3 - __bfloat162float(hh.y));
                *(__nv_bfloat162*)&Chi[(size_t)(row0 + 8) * N + col] = hh;
                *(__nv_bfloat162*)&Clo[(size_t)(row0 + 8) * N + col] = ll;
            }
        }
    }
}

// ---------------------------------------------------------------------------
// fused attention v4b: 2 q-rows per thread (rows tid, tid+160), 160 thr/CTA.
// Q loaded straight to registers (no smem stage); K/V broadcast LDS.
// launch_bounds(160,3) caps regs for 3 CTAs/SM.
// ---------------------------------------------------------------------------
#define ATTN_SMEM (2 * TOTAL_S * DK * 4)   // 40960 B

__global__ __launch_bounds__(160, 3) void attn_kernel(int use_prev, int wr)
{
    extern __shared__ float asm_f[];
    float* Ks = asm_f;
    float* Vs = Ks + TOTAL_S * DK;

    int bh = blockIdx.x;
    int bc = bh >> 4, h = bh & 15;
    int tid = threadIdx.x;             // q-rows tid and tid+160

    for (int i = tid; i < TOTAL_S * 4; i += 160) {
        int s = i >> 2, c = i & 3;
        const float4* src = (const float4*)&g_qkv[(size_t)(bc * TOTAL_S + s) * 768 + (h << 4)];
        *(float4*)&Ks[s * DK + c * 4] = src[64 + c];
        *(float4*)&Vs[s * DK + c * 4] = src[128 + c];
    }
    __syncthreads();

    const int ra = tid, rb = tid + 160;
    unsigned long long qa2[8], qb2[8];
    {
        const float4* qpa = (const float4*)&g_qkv[(size_t)(bc * TOTAL_S + ra) * 768 + (h << 4)];
        const float4* qpb = (const float4*)&g_qkv[(size_t)(bc * TOTAL_S + rb) * 768 + (h << 4)];
#pragma unroll
        for (int c = 0; c < 4; c++) {
            float4 va = qpa[c], vb = qpb[c];
            qa2[2 * c]     = pack2(va.x, va.y);
            qa2[2 * c + 1] = pack2(va.z, va.w);
            qb2[2 * c]     = pack2(vb.x, vb.y);
            qb2[2 * c + 1] = pack2(vb.z, vb.w);
        }
    }

    float ma = -1e30f, mb = -1e30f, da = 0.f, db = 0.f;
    unsigned long long oa2[8], ob2[8];
#pragma unroll
    for (int c = 0; c < 8; c++) { oa2[c] = 0ULL; ob2[c] = 0ULL; }

    float* srow = &g_scores[(size_t)bh * TOTAL_S * TOTAL_S];  // [kk][q]

#pragma unroll 1
    for (int blk = 0; blk < 40; blk++) {
        float sa[8], sb[8];
#pragma unroll
        for (int t = 0; t < 8; t++) {
            int kk = blk * 8 + t;
            const ulonglong2* kp = (const ulonglong2*)&Ks[kk * DK];
            unsigned long long aa2 = 0ULL, ab2 = 0ULL;
#pragma unroll
            for (int c = 0; c < 4; c++) {
                ulonglong2 kv = kp[c];                  // broadcast LDS.128
                FFMA2(aa2, qa2[2 * c], kv.x);
                FFMA2(aa2, qa2[2 * c + 1], kv.y);
                FFMA2(ab2, qb2[2 * c], kv.x);
                FFMA2(ab2, qb2[2 * c + 1], kv.y);
            }
            float lo, hi;
            unpack2(aa2, lo, hi);
            float s_a = (lo + hi) * ATTN_SCALE;
            unpack2(ab2, lo, hi);
            float s_b = (lo + hi) * ATTN_SCALE;
            if (use_prev) {
                s_a += srow[(size_t)kk * TOTAL_S + ra];
                s_b += srow[(size_t)kk * TOTAL_S + rb];
            }
            sa[t] = s_a; sb[t] = s_b;
            if (wr) {
                srow[(size_t)kk * TOTAL_S + ra] = s_a;
                srow[(size_t)kk * TOTAL_S + rb] = s_b;
            }
        }
        float bma = sa[0], bmb = sb[0];
#pragma unroll
        for (int t = 1; t < 8; t++) { bma = fmaxf(bma, sa[t]); bmb = fmaxf(bmb, sb[t]); }
        float mna = fmaxf(ma, bma), mnb = fmaxf(mb, bmb);
        float ca = __expf(ma - mna), cb = __expf(mb - mnb);
        da *= ca; db *= cb;
        unsigned long long ca2 = pack2(ca, ca), cb2 = pack2(cb, cb);
#pragma unroll
        for (int c = 0; c < 8; c++) { MUL2(oa2[c], oa2[c], ca2); MUL2(ob2[c], ob2[c], cb2); }
#pragma unroll
        for (int t = 0; t < 8; t++) {
            int kk = blk * 8 + t;
            float pa = __expf(sa[t] - mna), pb = __expf(sb[t] - mnb);
            da += pa; db += pb;
            unsigned long long pa2 = pack2(pa, pa), pb2 = pack2(pb, pb);
            const ulonglong2* vp = (const ulonglong2*)&Vs[kk * DK];
#pragma unroll
            for (int c = 0; c < 4; c++) {
                ulonglong2 vv = vp[c];                  // broadcast LDS.128
                FFMA2(oa2[2 * c], pa2, vv.x);
                FFMA2(oa2[2 * c + 1], pa2, vv.y);
                FFMA2(ob2[2 * c], pb2, vv.x);
                FFMA2(ob2[2 * c + 1], pb2, vv.y);
            }
        }
        ma = mna; mb = mnb;
    }

    float inva = 1.f / da, invb = 1.f / db;
    size_t oba = (size_t)(bc * TOTAL_S + ra) * D_MODEL + (h << 4);
    size_t obb = (size_t)(bc * TOTAL_S + rb) * D_MODEL + (h << 4);
#pragma unroll
    for (int c = 0; c < 8; c++) {
        float v0, v1;
        unpack2(oa2[c], v0, v1);
        v0 *= inva; v1 *= inva;
        __nv_bfloat162 hh, ll;
        hh.x = __float2bfloat16(v0); hh.y = __float2bfloat16(v1);
        ll.x = __float2bfloat16(v0 - __bfloat162float(hh.x));
        ll.y = __float2bfloat16(v1 - __bfloat162float(hh.y));
        *(__nv_bfloat162*)&g_o_hi[oba + c * 2] = hh;
        *(__nv_bfloat162*)&g_o_lo[oba + c * 2] = ll;
        unpack2(ob2[c], v0, v1);
        v0 *= invb; v1 *= invb;
        hh.x = __float2bfloat16(v0); hh.y = __float2bfloat16(v1);
        ll.x = __float2bfloat16(v0 - __bfloat162float(hh.x));
        ll.y = __float2bfloat16(v1 - __bfloat162float(hh.y));
        *(__nv_bfloat162*)&g_o_hi[obb + c * 2] = hh;
        *(__nv_bfloat162*)&g_o_lo[obb + c * 2] = ll;
    }
}

// ---------------------------------------------------------------------------
__global__ __launch_bounds__(256) void resid_ln_kernel(
    const float* __restrict__ delta,
    const float* __restrict__ gs, const float* __restrict__ gb)
{
    int row = blockIdx.x;
    int d = threadIdx.x;
    int warp = d >> 5, lane = d & 31;
    size_t idx = (size_t)row * D_MODEL + d;
    float t = g_u[idx] + delta[idx];

    __shared__ float sred[8];
    float ws = t;
#pragma unroll
    for (int o = 16; o; o >>= 1) ws += __shfl_xor_sync(0xffffffffu, ws, o);
    if (lane == 0) sred[warp] = ws;
    __syncthreads();
    float tot = 0.f;
#pragma unroll
    for (int i = 0; i < 8; i++) tot += sred[i];
    float mean = tot * (1.0f / D_MODEL);
    __syncthreads();

    float df = t - mean;
    ws = df * df;
#pragma unroll
    for (int o = 16; o; o >>= 1) ws += __shfl_xor_sync(0xffffffffu, ws, o);
    if (lane == 0) sred[warp] = ws;
    __syncthreads();
    tot = 0.f;
#pragma unroll
    for (int i = 0; i < 8; i++) tot += sred[i];
    float var = tot * (1.0f / D_MODEL);

    float y = df * rsqrtf(var + LN_EPS) * gs[d] + gb[d];
    g_u[idx] = y;
    __nv_bfloat16 h = __float2bfloat16(y);
    g_u_hi[idx] = h;
    g_u_lo[idx] = __float2bfloat16(y - __bfloat162float(h));
}

// ---------------------------------------------------------------------------
__global__ __launch_bounds__(96) void head_partial_kernel(const float* __restrict__ Wh)
{
    int d = blockIdx.x;
    int t = threadIdx.x;
    __shared__ float usm[BROWS][TOTAL_S];
    for (int i = t; i < BROWS * TOTAL_S; i += 96) {
        int bcc = i / TOTAL_S, s = i % TOTAL_S;
        usm[bcc][s] = g_u[(size_t)(bcc * TOTAL_S + s) * D_MODEL + d];
    }
    __syncthreads();
    float acc[BROWS];
#pragma unroll
    for (int b = 0; b < BROWS; b++) acc[b] = 0.f;
    for (int s = 0; s < TOTAL_S; s++) {
        float w = Wh[((size_t)d * TOTAL_S + s) * TGT + t];
#pragma unroll
        for (int b = 0; b < BROWS; b++) acc[b] += usm[b][s] * w;
    }
#pragma unroll
    for (int b = 0; b < BROWS; b++)
        g_part[((size_t)d * BROWS + b) * TGT + t] = acc[b];
}

__global__ __launch_bounds__(256) void head_reduce_kernel(
    const float* __restrict__ bh,
    const float* __restrict__ revin_w, const float* __restrict__ revin_b,
    float* __restrict__ out)
{
    int idx = blockIdx.x * blockDim.x + threadIdx.x;
    if (idx >= BROWS * TGT) return;
    int bcc = idx / TGT, t = idx % TGT;
    float acc = 0.f;
    for (int d = 0; d < D_MODEL; d++)
        acc += g_part[((size_t)d * BROWS + bcc) * TGT + t];
    acc += bh[t];
    int c = bcc & 7;
    out[idx] = (acc - revin_b[c]) / (revin_w[c] + 1e-10f) * g_std[bcc] + g_mean[bcc];
}

// ---------------------------------------------------------------------------
extern "C" void kernel_launch(void* const* d_in, const int* in_sizes, int n_in,
                              void* d_out, int out_size)
{
    const float* z       = (const float*)d_in[0];
    const float* revin_w = (const float*)d_in[1];
    const float* revin_b = (const float*)d_in[2];
    const float* Wf      = (const float*)d_in[3];
    const float* bf      = (const float*)d_in[4];
    const float* Wc      = (const float*)d_in[5];
    const float* bcoarse = (const float*)d_in[6];
    const float* Wpos    = (const float*)d_in[7];
    const float* WQ      = (const float*)d_in[8];
    const float* bQ      = (const float*)d_in[9];
    const float* WK      = (const float*)d_in[10];
    const float* bK      = (const float*)d_in[11];
    const float* WV      = (const float*)d_in[12];
    const float* bV      = (const float*)d_in[13];
    const float* WO      = (const float*)d_in[14];
    const float* bO      = (const float*)d_in[15];
    const float* ln1_s   = (const float*)d_in[16];
    const float* ln1_b   = (const float*)d_in[17];
    const float* ln2_s   = (const float*)d_in[18];
    const float* ln2_b   = (const float*)d_in[19];
    const float* F1      = (const float*)d_in[20];
    const float* c1      = (const float*)d_in[21];
    const float* F2      = (const float*)d_in[22];
    const float* c2      = (const float*)d_in[23];
    const float* Wh      = (const float*)d_in[24];
    const float* bh      = (const float*)d_in[25];
    float* out = (float*)d_out;

    float *u, *qkv, *tmp, *bqkv;
    __nv_bfloat16 *uh, *ul, *oh, *ol, *h1h, *h1l, *wth, *wtl;
    cudaGetSymbolAddress((void**)&u,    g_u);
    cudaGetSymbolAddress((void**)&qkv,  g_qkv);
    cudaGetSymbolAddress((void**)&tmp,  g_tmp);
    cudaGetSymbolAddress((void**)&bqkv, g_bqkv);
    cudaGetSymbolAddress((void**)&uh,   g_u_hi);
    cudaGetSymbolAddress((void**)&ul,   g_u_lo);
    cudaGetSymbolAddress((void**)&oh,   g_o_hi);
    cudaGetSymbolAddress((void**)&ol,   g_o_lo);
    cudaGetSymbolAddress((void**)&h1h,  g_h1_hi);
    cudaGetSymbolAddress((void**)&h1l,  g_h1_lo);
    cudaGetSymbolAddress((void**)&wth,  g_wt_hi);
    cudaGetSymbolAddress((void**)&wtl,  g_wt_lo);

    const int SMEM64 = 2 * (2 * 64 * ASTRIDE * 2 + 2 * 128 * ASTRIDE * 2);  // 110592
    cudaFuncSetAttribute(gemm_tc<0,64>, cudaFuncAttributeMaxDynamicSharedMemorySize, SMEM64);
    cudaFuncSetAttribute(gemm_tc<1,64>, cudaFuncAttributeMaxDynamicSharedMemorySize, SMEM64);
    cudaFuncSetAttribute(attn_kernel,   cudaFuncAttributeMaxDynamicSharedMemorySize, ATTN_SMEM);

    // launch order: 0 wsplit(+bias+stats), 1 embed, 2 QKV gemm, 3 attn
    wsplit_all_kernel<<<dim3(256, 8, NLAYERS), 256>>>(WQ, WK, WV, WO, F1, F2,
                                                      bQ, bK, bV, z);
    embed_kernel<<<dim3(TOTAL_S, BROWS), 256>>>(z, revin_w, revin_b,
                                                Wf, bf, Wc, bcoarse, Wpos);

    for (int l = 0; l < NLAYERS; l++) {
        const size_t L = (size_t)l * WSTRIDE;
        gemm_tc<0,64><<<dim3(6, 80), 256, SMEM64>>>(
            uh, ul, wth + L + WOFF_Q, wtl + L + WOFF_Q,
            bqkv + l * 768, qkv, nullptr, nullptr, 768, D_MODEL);
        attn_kernel<<<BROWS * NHEADS, 160, ATTN_SMEM>>>(
            l > 0 ? 1 : 0, l < NLAYERS - 1 ? 1 : 0);
        gemm_tc<0,64><<<dim3(2, 80), 256, SMEM64>>>(
            oh, ol, wth + L + WOFF_O, wtl + L + WOFF_O,
            bO + l * D_MODEL, tmp, nullptr, nullptr, D_MODEL, D_MODEL);
        resid_ln_kernel<<<SEQ, 256>>>(tmp, ln1_s + l * D_MODEL, ln1_b + l * D_MODEL);
        gemm_tc<1,64><<<dim3(8, 80), 256, SMEM64>>>(
            uh, ul, wth + L + WOFF_F1, wtl + L + WOFF_F1,
            c1 + l * DFF, nullptr, h1h, h1l, DFF, D_MODEL);
        gemm_tc<0,64><<<dim3(2, 80), 256, SMEM64>>>(
            h1h, h1l, wth + L + WOFF_F2, wtl + L + WOFF_F2,
            c2 + l * D_MODEL, tmp, nullptr, nullptr, D_MODEL, DFF);
        resid_ln_kernel<<<SEQ, 256>>>(tmp, ln2_s + l * D_MODEL, ln2_b + l * D_MODEL);
    }

    head_partial_kernel<<<D_MODEL, 96>>>(Wh);
    head_reduce_kernel<<<6, 256>>>(bh, revin_w, revin_b, out);
}